// round 1
// baseline (speedup 1.0000x reference)
#include <cuda_runtime.h>
#include <math.h>

#define NE    8
#define NB    100000
#define DIM   1024
#define NSUP  128
#define KSEL  15000u

// ---------------- scratch (static device globals; no allocs) ----------------
__device__ float    g_q[NE][DIM];          // (unnormalized) support mean per episode
__device__ float    g_sim[NE * NB];        // sim[e][row] = q_e . b_row_hat
__device__ float    g_invnorm[NB];         // 1/||base_row||
__device__ unsigned g_hist1[NE][65536];
__device__ unsigned g_hist2[NE][65536];
__device__ unsigned g_bin1[NE];
__device__ unsigned g_r1[NE];
__device__ unsigned g_thr_key[NE];
__device__ int      g_tiecut[NE];
__device__ float    g_approx[NE][DIM];

__device__ __forceinline__ unsigned tokey(float f) {
    unsigned b = __float_as_uint(f);
    return b ^ ((unsigned)((int)b >> 31) | 0x80000000u);   // order-preserving float->uint
}

// ---------------- init: zero histograms + accumulators ----------------
__global__ void kInit() {
    unsigned idx = blockIdx.x * blockDim.x + threadIdx.x;
    unsigned stride = gridDim.x * blockDim.x;
    unsigned* h1 = &g_hist1[0][0];
    unsigned* h2 = &g_hist2[0][0];
    for (unsigned i = idx; i < NE * 65536u; i += stride) { h1[i] = 0u; h2[i] = 0u; }
    float* ap = &g_approx[0][0];
    for (unsigned i = idx; i < NE * DIM; i += stride) ap[i] = 0.0f;
}

// ---------------- A: per-episode support mean of normalized rows ----------------
__global__ void __launch_bounds__(1024) kA(const float* __restrict__ feats) {
    int e = blockIdx.x;
    int tid = threadIdx.x, lane = tid & 31, wid = tid >> 5;
    __shared__ float s_inv[NSUP];
    const float* fe = feats + (size_t)e * DIM * DIM;
    #pragma unroll
    for (int rr = 0; rr < NSUP / 32; rr++) {
        int r = wid + rr * 32;
        const float4* row4 = (const float4*)(fe + (size_t)r * DIM);
        float s = 0.f;
        #pragma unroll
        for (int k = 0; k < 8; k++) {
            float4 v = row4[k * 32 + lane];
            s += v.x * v.x + v.y * v.y + v.z * v.z + v.w * v.w;
        }
        #pragma unroll
        for (int o = 16; o > 0; o >>= 1) s += __shfl_xor_sync(0xFFFFFFFFu, s, o);
        if (lane == 0) s_inv[r] = rsqrtf(fmaxf(s, 1e-24f));
    }
    __syncthreads();
    float acc = 0.f;
    #pragma unroll 8
    for (int r = 0; r < NSUP; r++) acc += fe[(size_t)r * DIM + tid] * s_inv[r];
    g_q[e][tid] = acc;   // scaling of q cancels everywhere downstream
}

// ---------------- B: sims for all base rows (warp handles 4 rows) ----------------
__global__ void __launch_bounds__(128) kB(const float* __restrict__ base) {
    __shared__ float4 sq[NE * 256];   // 32 KB: q as float4
    for (int i = threadIdx.x; i < NE * 256; i += 128) sq[i] = ((const float4*)g_q)[i];
    __syncthreads();
    int lane = threadIdx.x & 31;
    int gw = (blockIdx.x * 128 + threadIdx.x) >> 5;
    int nw = (gridDim.x * 128) >> 5;
    for (int g = gw; g < NB / 4; g += nw) {
        const float4* p0 = (const float4*)(base + (size_t)(4 * g) * DIM);
        const float4* p1 = p0 + 256;
        const float4* p2 = p0 + 512;
        const float4* p3 = p0 + 768;
        float acc[4][8];
        float ss[4];
        #pragma unroll
        for (int r = 0; r < 4; r++) {
            ss[r] = 0.f;
            #pragma unroll
            for (int e = 0; e < 8; e++) acc[r][e] = 0.f;
        }
        #pragma unroll 2
        for (int k = 0; k < 8; k++) {
            float4 v0 = p0[k * 32 + lane];
            float4 v1 = p1[k * 32 + lane];
            float4 v2 = p2[k * 32 + lane];
            float4 v3 = p3[k * 32 + lane];
            ss[0] += v0.x * v0.x + v0.y * v0.y + v0.z * v0.z + v0.w * v0.w;
            ss[1] += v1.x * v1.x + v1.y * v1.y + v1.z * v1.z + v1.w * v1.w;
            ss[2] += v2.x * v2.x + v2.y * v2.y + v2.z * v2.z + v2.w * v2.w;
            ss[3] += v3.x * v3.x + v3.y * v3.y + v3.z * v3.z + v3.w * v3.w;
            #pragma unroll
            for (int e = 0; e < 8; e++) {
                float4 q = sq[e * 256 + k * 32 + lane];
                acc[0][e] += v0.x * q.x + v0.y * q.y + v0.z * q.z + v0.w * q.w;
                acc[1][e] += v1.x * q.x + v1.y * q.y + v1.z * q.z + v1.w * q.w;
                acc[2][e] += v2.x * q.x + v2.y * q.y + v2.z * q.z + v2.w * q.w;
                acc[3][e] += v3.x * q.x + v3.y * q.y + v3.z * q.z + v3.w * q.w;
            }
        }
        #pragma unroll
        for (int r = 0; r < 4; r++) {
            float s = ss[r];
            #pragma unroll
            for (int o = 16; o > 0; o >>= 1) s += __shfl_xor_sync(0xFFFFFFFFu, s, o);
            float inv = rsqrtf(fmaxf(s, 1e-24f));
            if (lane == 0) g_invnorm[4 * g + r] = inv;
            #pragma unroll
            for (int e = 0; e < 8; e++) {
                float d = acc[r][e];
                #pragma unroll
                for (int o = 16; o > 0; o >>= 1) d += __shfl_xor_sync(0xFFFFFFFFu, d, o);
                if (lane == 0) g_sim[e * NB + 4 * g + r] = d * inv;
            }
        }
    }
}

// ---------------- C: exact K-th value via 2-level 16-bit radix histograms ------
__global__ void kHist1() {
    int e = blockIdx.y;
    int i = blockIdx.x * blockDim.x + threadIdx.x;
    if (i < NB) {
        unsigned key = tokey(g_sim[e * NB + i]);
        atomicAdd(&g_hist1[e][key >> 16], 1u);
    }
}

// descending-order selection inside a 65536-bin histogram; block of 1024 threads
__device__ __forceinline__ void find_desc(const unsigned* __restrict__ hist, unsigned target,
                                          unsigned* obin, unsigned* orr) {
    int t = threadIdx.x, lane = t & 31, wid = t >> 5;
    unsigned base = (unsigned)t * 64u;
    unsigned part = 0;
    #pragma unroll 8
    for (int j = 0; j < 64; j++) part += hist[base + j];
    unsigned x = part;
    #pragma unroll
    for (int o = 1; o < 32; o <<= 1) { unsigned y = __shfl_up_sync(0xFFFFFFFFu, x, o); if (lane >= o) x += y; }
    __shared__ unsigned s_ws[32];
    __shared__ unsigned s_total;
    if (lane == 31) s_ws[wid] = x;
    __syncthreads();
    if (wid == 0) {
        unsigned w = s_ws[lane];
        #pragma unroll
        for (int o = 1; o < 32; o <<= 1) { unsigned y = __shfl_up_sync(0xFFFFFFFFu, w, o); if (lane >= o) w += y; }
        s_ws[lane] = w;
        if (lane == 31) s_total = w;
    }
    __syncthreads();
    unsigned incl = x + (wid ? s_ws[wid - 1] : 0u);
    unsigned above = s_total - incl;              // count in bins strictly above this segment
    if (above < target && target <= above + part) {
        unsigned cum = above;
        for (int j = 63; j >= 0; j--) {
            unsigned c = hist[base + j];
            if (cum + c >= target) { *obin = base + j; *orr = target - cum; break; }
            cum += c;
        }
    }
}

__global__ void __launch_bounds__(1024) kFind1() {
    int e = blockIdx.x;
    find_desc(g_hist1[e], KSEL, &g_bin1[e], &g_r1[e]);
}

__global__ void kHist2() {
    int e = blockIdx.y;
    unsigned b1 = g_bin1[e];
    int i = blockIdx.x * blockDim.x + threadIdx.x;
    if (i < NB) {
        unsigned key = tokey(g_sim[e * NB + i]);
        if ((key >> 16) == b1) atomicAdd(&g_hist2[e][key & 0xFFFFu], 1u);
    }
}

__global__ void __launch_bounds__(1024) kFind2() {
    int e = blockIdx.x;
    __shared__ unsigned s_bin, s_r;
    find_desc(g_hist2[e], g_r1[e], &s_bin, &s_r);
    __syncthreads();
    unsigned thr = (g_bin1[e] << 16) | s_bin;
    unsigned r2 = s_r;                       // number of ties at thr to include
    if (threadIdx.x == 0) g_thr_key[e] = thr;
    __shared__ int s_cnt;
    __shared__ int s_idx[2048];
    if (threadIdx.x == 0) s_cnt = 0;
    __syncthreads();
    const float* sims = g_sim + (size_t)e * NB;
    for (int i = threadIdx.x; i < NB; i += 1024) {
        if (tokey(sims[i]) == thr) {
            int p = atomicAdd(&s_cnt, 1);
            if (p < 2048) s_idx[p] = i;
        }
    }
    __syncthreads();
    int cnt = min(s_cnt, 2048);
    // jax top_k breaks ties by lowest index: keep the r2 smallest tie indices
    for (int i = threadIdx.x; i < cnt; i += 1024) {
        int my = s_idx[i];
        int rank = 0;
        for (int j = 0; j < cnt; j++) rank += (s_idx[j] < my) ? 1 : 0;
        if (rank == (int)r2 - 1) g_tiecut[e] = my;
    }
}

// ---------------- D: single-pass weighted accumulation over base ----------------
__global__ void __launch_bounds__(256) kD(const float* __restrict__ base) {
    __shared__ float s_w[32][8];           // weights for a 32-row tile
    int tid = threadIdx.x;
    int we = tid >> 5, wr = tid & 31;      // warp's episode / row within tile
    float4 acc[8];
    #pragma unroll
    for (int e = 0; e < 8; e++) acc[e] = make_float4(0.f, 0.f, 0.f, 0.f);
    unsigned thr = g_thr_key[we];
    int cut = g_tiecut[we];
    const float4* b4 = (const float4*)base;
    for (int tile = blockIdx.x; tile < NB / 32; tile += gridDim.x) {
        int row0 = tile * 32;
        {
            int row = row0 + wr;
            float sim = g_sim[we * NB + row];
            unsigned key = tokey(sim);
            bool sel = (key > thr) || (key == thr && row <= cut);
            s_w[wr][we] = sel ? (sqrtf(fmaxf(sim, 0.f)) * g_invnorm[row]) : 0.f;
        }
        __syncthreads();
        #pragma unroll 2
        for (int r = 0; r < 32; r++) {
            float4 wlo = *(const float4*)(&s_w[r][0]);
            float4 whi = *(const float4*)(&s_w[r][4]);
            unsigned any = __float_as_uint(wlo.x) | __float_as_uint(wlo.y) |
                           __float_as_uint(wlo.z) | __float_as_uint(wlo.w) |
                           __float_as_uint(whi.x) | __float_as_uint(whi.y) |
                           __float_as_uint(whi.z) | __float_as_uint(whi.w);
            if (any) {                                  // warp-uniform branch
                float4 v = b4[(size_t)(row0 + r) * 256 + tid];
                #define ACCUM(idx, wv) \
                    acc[idx].x += (wv) * v.x; acc[idx].y += (wv) * v.y; \
                    acc[idx].z += (wv) * v.z; acc[idx].w += (wv) * v.w;
                ACCUM(0, wlo.x) ACCUM(1, wlo.y) ACCUM(2, wlo.z) ACCUM(3, wlo.w)
                ACCUM(4, whi.x) ACCUM(5, whi.y) ACCUM(6, whi.z) ACCUM(7, whi.w)
                #undef ACCUM
            }
        }
        __syncthreads();
    }
    #pragma unroll
    for (int e = 0; e < 8; e++) {
        atomicAdd(&g_approx[e][4 * tid + 0], acc[e].x);
        atomicAdd(&g_approx[e][4 * tid + 1], acc[e].y);
        atomicAdd(&g_approx[e][4 * tid + 2], acc[e].z);
        atomicAdd(&g_approx[e][4 * tid + 3], acc[e].w);
    }
}

// ---------------- E: normalize approx ----------------
__global__ void __launch_bounds__(256) kE() {
    int e = blockIdx.x, tid = threadIdx.x;
    float4* a4 = (float4*)g_approx[e];
    float4 v = a4[tid];
    float ss = v.x * v.x + v.y * v.y + v.z * v.z + v.w * v.w;
    int lane = tid & 31, wid = tid >> 5;
    #pragma unroll
    for (int o = 16; o > 0; o >>= 1) ss += __shfl_xor_sync(0xFFFFFFFFu, ss, o);
    __shared__ float s_s[8];
    __shared__ float s_inv;
    if (lane == 0) s_s[wid] = ss;
    __syncthreads();
    if (tid == 0) {
        float t = 0.f;
        for (int i = 0; i < 8; i++) t += s_s[i];
        s_inv = rsqrtf(fmaxf(t, 1e-24f));
    }
    __syncthreads();
    float inv = s_inv;
    v.x *= inv; v.y *= inv; v.z *= inv; v.w *= inv;
    a4[tid] = v;
}

// ---------------- F: orthogonalize every feature row ----------------
__global__ void __launch_bounds__(256) kF(const float* __restrict__ feats, float* __restrict__ out) {
    int b = blockIdx.x;
    int e = b >> 7;
    int lane = threadIdx.x & 31, warp = threadIdx.x >> 5;
    int rowInEp = (b & 127) * 8 + warp;
    size_t off = ((size_t)e * DIM + rowInEp) * DIM;
    const float4* f4 = (const float4*)(feats + off);
    float4* o4 = (float4*)(out + off);
    const float4* a4 = (const float4*)g_approx[e];
    float4 v[8], a[8];
    float ss = 0.f, dd = 0.f;
    #pragma unroll
    for (int k = 0; k < 8; k++) {
        v[k] = f4[k * 32 + lane];
        a[k] = a4[k * 32 + lane];
        ss += v[k].x * v[k].x + v[k].y * v[k].y + v[k].z * v[k].z + v[k].w * v[k].w;
        dd += v[k].x * a[k].x + v[k].y * a[k].y + v[k].z * a[k].z + v[k].w * a[k].w;
    }
    #pragma unroll
    for (int o = 16; o > 0; o >>= 1) {
        ss += __shfl_xor_sync(0xFFFFFFFFu, ss, o);
        dd += __shfl_xor_sync(0xFFFFFFFFu, dd, o);
    }
    float invf = rsqrtf(fmaxf(ss, 1e-24f));
    float c = dd * invf;                                  // cos(f_hat, a_hat)
    float sc = rsqrtf(fmaxf(1.0f - c * c, 1e-24f));       // analytic ||f_hat - c a_hat||
    #pragma unroll
    for (int k = 0; k < 8; k++) {
        float4 r;
        r.x = (v[k].x * invf - c * a[k].x) * sc;
        r.y = (v[k].y * invf - c * a[k].y) * sc;
        r.z = (v[k].z * invf - c * a[k].z) * sc;
        r.w = (v[k].w * invf - c * a[k].w) * sc;
        o4[k * 32 + lane] = r;
    }
}

// ---------------- launch ----------------
extern "C" void kernel_launch(void* const* d_in, const int* in_sizes, int n_in,
                              void* d_out, int out_size) {
    const float* feats = (const float*)d_in[0];
    const float* base  = (const float*)d_in[1];
    float* out = (float*)d_out;
    (void)in_sizes; (void)n_in; (void)out_size;

    kInit<<<1024, 512>>>();
    kA<<<NE, 1024>>>(feats);
    kB<<<1480, 128>>>(base);
    kHist1<<<dim3(196, NE), 512>>>();
    kFind1<<<NE, 1024>>>();
    kHist2<<<dim3(196, NE), 512>>>();
    kFind2<<<NE, 1024>>>();
    kD<<<592, 256>>>(base);
    kE<<<NE, 256>>>();
    kF<<<1024, 256>>>(feats, out);
}